// round 15
// baseline (speedup 1.0000x reference)
#include <cuda_runtime.h>
#include <math.h>

#define Bn   128
#define Dn   1024
#define Hn   256
#define Mn   100
#define KSEL 5
#define EPSf 1e-5f
#define MD   (Mn*Dn)      // 102400
#define BM   (Bn*Mn)      // 12800

// --------- scratch (no allocations allowed) ----------
__device__ float g_h2t[Hn*Bn];        // h2 transposed: [k][b]
__device__ int   g_idx[BM*KSEL];
__device__ float g_val[BM*KSEL];

// --------- block reductions ----------
__device__ __forceinline__ float block_reduce_sum(float v, float* red){
    int t = threadIdx.x;
    int nw = blockDim.x >> 5;
    #pragma unroll
    for(int o=16;o>0;o>>=1) v += __shfl_down_sync(0xffffffffu, v, o);
    if((t&31)==0) red[t>>5] = v;
    __syncthreads();
    if(t < 32){
        float s = (t < nw) ? red[t] : 0.f;
        #pragma unroll
        for(int o=16;o>0;o>>=1) s += __shfl_down_sync(0xffffffffu, s, o);
        if(t==0) red[0] = s;
    }
    __syncthreads();
    float s = red[0];
    __syncthreads();
    return s;
}

__device__ __forceinline__ float block_reduce_max(float v, float* red){
    int t = threadIdx.x;
    int nw = blockDim.x >> 5;
    #pragma unroll
    for(int o=16;o>0;o>>=1) v = fmaxf(v, __shfl_down_sync(0xffffffffu, v, o));
    if((t&31)==0) red[t>>5] = v;
    __syncthreads();
    if(t < 32){
        float s = (t < nw) ? red[t] : -3.402823466e38f;
        #pragma unroll
        for(int o=16;o>0;o>>=1) s = fmaxf(s, __shfl_down_sync(0xffffffffu, s, o));
        if(t==0) red[0] = s;
    }
    __syncthreads();
    float s = red[0];
    __syncthreads();
    return s;
}

// =====================================================================
// K1: generator front:  h2 = relu(LN(relu(LN(x@gW1+gb1))@gW2+gb2))
// one block per batch row b, 256 threads
// =====================================================================
__global__ __launch_bounds__(256) void k_gen_front(
    const float* __restrict__ x,
    const float* __restrict__ gW1, const float* __restrict__ gb1,
    const float* __restrict__ ln1s, const float* __restrict__ ln1b,
    const float* __restrict__ gW2, const float* __restrict__ gb2,
    const float* __restrict__ ln2s, const float* __restrict__ ln2b)
{
    const int b = blockIdx.x, t = threadIdx.x;
    __shared__ float xs[Dn];
    __shared__ float h1[2*Hn];   // 512
    __shared__ float red[32];

    for(int i=t;i<Dn;i+=256) xs[i] = x[b*Dn+i];
    __syncthreads();

    float a0 = gb1[t], a1 = gb1[t+256];
    #pragma unroll 4
    for(int d=0; d<Dn; ++d){
        float xv = xs[d];
        a0 = fmaf(xv, gW1[d*512 + t      ], a0);
        a1 = fmaf(xv, gW1[d*512 + t + 256], a1);
    }
    float mu = block_reduce_sum(a0+a1, red) * (1.f/512.f);
    float d0 = a0-mu, d1 = a1-mu;
    float var = block_reduce_sum(d0*d0 + d1*d1, red) * (1.f/512.f);
    float rs = rsqrtf(var + EPSf);
    h1[t]     = fmaxf(d0*rs*ln1s[t]     + ln1b[t],     0.f);
    h1[t+256] = fmaxf(d1*rs*ln1s[t+256] + ln1b[t+256], 0.f);
    __syncthreads();

    float a = gb2[t];
    #pragma unroll 4
    for(int k=0;k<512;++k) a = fmaf(h1[k], gW2[k*256 + t], a);
    float mu2 = block_reduce_sum(a, red) * (1.f/256.f);
    float dd = a - mu2;
    float v2 = block_reduce_sum(dd*dd, red) * (1.f/256.f);
    float h2v = fmaxf(dd*rsqrtf(v2+EPSf)*ln2s[t] + ln2b[t], 0.f);
    g_h2t[t*Bn + b] = h2v;   // transposed for GEMM
}

// =====================================================================
// K2a: logits GEMM:  C[128, 102400] = h2[128,256] @ gW3[256,102400] + gb3
// block tile 128(b) x 128(n), 256 threads, 8x8 microtile, k-chunks of 32
// =====================================================================
__global__ __launch_bounds__(256) void k_gemm_logits(
    const float* __restrict__ W, const float* __restrict__ gb3,
    float* __restrict__ logits)
{
    const int n0 = blockIdx.x * 128;
    const int t  = threadIdx.x;
    __shared__ __align__(16) float As[32][128];
    __shared__ __align__(16) float Ws[32][132];

    const int b0 = (t >> 4) * 8;     // 0..120
    const int d0 = (t & 15) * 8;     // 0..120

    float acc[8][8];
    #pragma unroll
    for(int i=0;i<8;i++)
        #pragma unroll
        for(int j=0;j<8;j++) acc[i][j] = 0.f;

    for(int kc=0; kc<Hn; kc+=32){
        // A chunk: As[kk][bb] = h2t[(kc+kk)*128 + bb]   (coalesced, no conflicts)
        #pragma unroll
        for(int i=t; i<32*128; i+=256){
            int kk = i >> 7, bb = i & 127;
            As[kk][bb] = g_h2t[(kc+kk)*Bn + bb];
        }
        // W chunk: Ws[kk][dd] = W[(kc+kk)*102400 + n0 + dd]  (float4)
        #pragma unroll
        for(int i=t; i<32*32; i+=256){
            int kk = i >> 5, v4 = i & 31;
            float4 w4 = __ldg((const float4*)(W + (size_t)(kc+kk)*MD + n0) + v4);
            *((float4*)&Ws[kk][v4*4]) = w4;
        }
        __syncthreads();

        #pragma unroll
        for(int k=0;k<32;k++){
            float ra[8], rw[8];
            *((float4*)&ra[0]) = *((const float4*)&As[k][b0]);
            *((float4*)&ra[4]) = *((const float4*)&As[k][b0+4]);
            *((float4*)&rw[0]) = *((const float4*)&Ws[k][d0]);
            *((float4*)&rw[4]) = *((const float4*)&Ws[k][d0+4]);
            #pragma unroll
            for(int i=0;i<8;i++)
                #pragma unroll
                for(int j=0;j<8;j++)
                    acc[i][j] = fmaf(ra[i], rw[j], acc[i][j]);
        }
        __syncthreads();
    }

    // epilogue: +gb3, write logits
    #pragma unroll
    for(int i=0;i<8;i++){
        size_t base = (size_t)(b0+i)*MD + n0 + d0;
        #pragma unroll
        for(int j=0;j<8;j+=4){
            float4 o;
            o.x = acc[i][j+0] + gb3[n0+d0+j+0];
            o.y = acc[i][j+1] + gb3[n0+d0+j+1];
            o.z = acc[i][j+2] + gb3[n0+d0+j+2];
            o.w = acc[i][j+3] + gb3[n0+d0+j+3];
            *((float4*)(logits + base + j)) = o;
        }
    }
}

// =====================================================================
// K2b: per (b,m) row: z=(logits+gumbel)*2 ; probs=softmax(z) ; top-5 of z
// one block (128 threads) per row, 8 elements/thread
// =====================================================================
__global__ __launch_bounds__(128) void k_softmax_topk(
    const float* __restrict__ logits, const float* __restrict__ gumbel,
    const float* __restrict__ x, float* __restrict__ probs)
{
    const int row = blockIdx.x;          // b*M + m
    const int b   = row / Mn;
    const int t   = threadIdx.x;
    const float4* l4 = (const float4*)(logits + (size_t)row*Dn);
    const float4* g4 = (const float4*)(gumbel + (size_t)row*Dn);

    float s[8];
    {
        float4 a = l4[t*2],   c = g4[t*2];
        float4 a2= l4[t*2+1], c2= g4[t*2+1];
        s[0]=(a.x+c.x)*2.f;  s[1]=(a.y+c.y)*2.f;  s[2]=(a.z+c.z)*2.f;  s[3]=(a.w+c.w)*2.f;
        s[4]=(a2.x+c2.x)*2.f;s[5]=(a2.y+c2.y)*2.f;s[6]=(a2.z+c2.z)*2.f;s[7]=(a2.w+c2.w)*2.f;
    }

    __shared__ float red[32];
    float mx = s[0];
    #pragma unroll
    for(int i=1;i<8;i++) mx = fmaxf(mx, s[i]);
    mx = block_reduce_max(mx, red);

    float e[8]; float sum = 0.f;
    #pragma unroll
    for(int i=0;i<8;i++){ e[i] = expf(s[i]-mx); sum += e[i]; }
    sum = block_reduce_sum(sum, red);
    float inv = 1.f/sum;

    float4* p4 = (float4*)(probs + (size_t)row*Dn);
    float4 p0 = make_float4(e[0]*inv, e[1]*inv, e[2]*inv, e[3]*inv);
    float4 p1 = make_float4(e[4]*inv, e[5]*inv, e[6]*inv, e[7]*inv);
    p4[t*2]   = p0;
    p4[t*2+1] = p1;

    // ---- top-5 via 5 masked argmax passes, jax tie-break (lower index) ----
    __shared__ float rv[4];
    __shared__ int   ri[4];
    __shared__ int   sel;
    const int base_d = t*8;
    for(int r=0;r<KSEL;r++){
        float bv = -3.402823466e38f; int bi = Dn;
        #pragma unroll
        for(int i=0;i<8;i++){
            if(s[i] > bv || (s[i] == bv && base_d+i < bi)){ bv = s[i]; bi = base_d+i; }
        }
        #pragma unroll
        for(int o=16;o>0;o>>=1){
            float ov = __shfl_down_sync(0xffffffffu, bv, o);
            int   oi = __shfl_down_sync(0xffffffffu, bi, o);
            if(ov > bv || (ov == bv && oi < bi)){ bv = ov; bi = oi; }
        }
        if((t&31)==0){ rv[t>>5] = bv; ri[t>>5] = bi; }
        __syncthreads();
        if(t==0){
            #pragma unroll
            for(int w=1;w<4;w++){
                if(rv[w] > bv || (rv[w] == bv && ri[w] < bi)){ bv = rv[w]; bi = ri[w]; }
            }
            sel = bi;
            g_idx[row*KSEL + r] = bi;
            g_val[row*KSEL + r] = x[b*Dn + bi];
        }
        __syncthreads();
        int sd = sel;
        if(sd >= base_d && sd < base_d+8) s[sd-base_d] = -3.402823466e38f;
        __syncthreads();
    }
}

// =====================================================================
// K3: scorer + synergy heads, 16 (b,m)-rows per block, 256 threads
// =====================================================================
#define R3 16
__global__ __launch_bounds__(256) void k_heads(
    const float* __restrict__ sW1, const float* __restrict__ sb1,
    const float* __restrict__ sW2, const float* __restrict__ sb2,
    const float* __restrict__ sW3, const float* __restrict__ sb3,
    const float* __restrict__ yW1, const float* __restrict__ yb1,
    const float* __restrict__ yW2, const float* __restrict__ yb2,
    float* __restrict__ scores, float* __restrict__ syns)
{
    const int row0 = blockIdx.x * R3;
    const int t = threadIdx.x;
    __shared__ float hs[R3][Hn];     // 16 KB
    __shared__ float hy[R3][Hn];     // 16 KB
    __shared__ float h2s[R3][128];   // 8 KB
    __shared__ int   sidx[R3][KSEL];
    __shared__ float sval[R3][KSEL];

    if(t < R3*KSEL){
        int r = t / KSEL, j = t % KSEL;
        sidx[r][j] = g_idx[(row0+r)*KSEL + j];
        sval[r][j] = g_val[(row0+r)*KSEL + j];
    }
    __syncthreads();

    // stage 1: hs/hy = relu(sum_j val_j * W1[row_j, :] + b1)  (5-sparse gather)
    for(int r=0;r<R3;r++){
        float a = sb1[t], c = yb1[t];
        #pragma unroll
        for(int j=0;j<KSEL;j++){
            size_t w = (size_t)(j*Dn + sidx[r][j]) * Hn + t;
            float v = sval[r][j];
            a = fmaf(v, __ldg(sW1 + w), a);
            c = fmaf(v, __ldg(yW1 + w), c);
        }
        hs[r][t] = fmaxf(a, 0.f);
        hy[r][t] = fmaxf(c, 0.f);
    }
    __syncthreads();

    // stage 2: h2s[r] = relu(hs[r] @ sW2 + sb2), 8 rows per half-block
    {
        const int c  = t & 127;
        const int rb = (t >> 7) * 8;
        float acc[8] = {0,0,0,0,0,0,0,0};
        for(int k=0;k<Hn;k++){
            float w = __ldg(sW2 + k*128 + c);
            #pragma unroll
            for(int rr=0;rr<8;rr++) acc[rr] = fmaf(hs[rb+rr][k], w, acc[rr]);
        }
        float bb = sb2[c];
        #pragma unroll
        for(int rr=0;rr<8;rr++) h2s[rb+rr][c] = fmaxf(acc[rr] + bb, 0.f);
    }
    __syncthreads();

    // stage 3: final dots, 16 threads per row
    {
        const int r = t >> 4;     // 0..15
        const int g = t & 15;     // 0..15
        float ds = 0.f, dy = 0.f;
        #pragma unroll
        for(int i=0;i<8;i++)  ds = fmaf(h2s[r][g*8+i],  sW3[g*8+i],  ds);
        #pragma unroll
        for(int i=0;i<16;i++) dy = fmaf(hy[r][g*16+i], yW2[g*16+i], dy);
        #pragma unroll
        for(int o=8;o>0;o>>=1){
            ds += __shfl_down_sync(0xffffffffu, ds, o, 16);
            dy += __shfl_down_sync(0xffffffffu, dy, o, 16);
        }
        if(g==0){
            scores[row0+r] = 1.f/(1.f + expf(-(ds + sb3[0])));
            syns[row0+r]   = tanhf(dy + yb2[0]);
        }
    }
}

// =====================================================================
extern "C" void kernel_launch(void* const* d_in, const int* in_sizes, int n_in,
                              void* d_out, int out_size)
{
    const float* x    = (const float*)d_in[0];
    const float* gum  = (const float*)d_in[1];
    const float* gW1  = (const float*)d_in[2];
    const float* gb1  = (const float*)d_in[3];
    const float* ln1s = (const float*)d_in[4];
    const float* ln1b = (const float*)d_in[5];
    const float* gW2  = (const float*)d_in[6];
    const float* gb2  = (const float*)d_in[7];
    const float* ln2s = (const float*)d_in[8];
    const float* ln2b = (const float*)d_in[9];
    const float* gW3  = (const float*)d_in[10];
    const float* gb3  = (const float*)d_in[11];
    const float* sW1  = (const float*)d_in[12];
    const float* sb1  = (const float*)d_in[13];
    const float* sW2  = (const float*)d_in[14];
    const float* sb2  = (const float*)d_in[15];
    const float* sW3  = (const float*)d_in[16];
    const float* sb3  = (const float*)d_in[17];
    const float* yW1  = (const float*)d_in[18];
    const float* yb1  = (const float*)d_in[19];
    const float* yW2  = (const float*)d_in[20];
    const float* yb2  = (const float*)d_in[21];

    float* out    = (float*)d_out;
    float* probs  = out;                               // [B,M,D]
    float* scores = out + (size_t)Bn*Mn*Dn;            // [B,M]
    float* syns   = scores + Bn*Mn;                    // [B,M]
    float* logits = syns + Bn*Mn;                      // [B,M,D]

    k_gen_front<<<Bn, 256>>>(x, gW1, gb1, ln1s, ln1b, gW2, gb2, ln2s, ln2b);
    k_gemm_logits<<<MD/128, 256>>>(gW3, gb3, logits);
    k_softmax_topk<<<Bn*Mn, 128>>>(logits, gum, x, probs);
    k_heads<<<(Bn*Mn)/R3, 256>>>(sW1, sb1, sW2, sb2, sW3, sb3,
                                 yW1, yb1, yW2, yb2, scores, syns);
}

// round 16
// speedup vs baseline: 1.0043x; 1.0043x over previous
#include <cuda_runtime.h>
#include <math.h>

#define Bn   128
#define Dn   1024
#define Hn   256
#define Mn   100
#define KSEL 5
#define EPSf 1e-5f
#define MD   (Mn*Dn)      // 102400
#define BM   (Bn*Mn)      // 12800

// --------- scratch (no allocations allowed) ----------
__device__ float g_h2t[Hn*Bn];        // h2 transposed: [k][b]
__device__ int   g_idx[BM*KSEL];
__device__ float g_val[BM*KSEL];

// --------- block reductions ----------
__device__ __forceinline__ float block_reduce_sum(float v, float* red){
    int t = threadIdx.x;
    int nw = blockDim.x >> 5;
    #pragma unroll
    for(int o=16;o>0;o>>=1) v += __shfl_down_sync(0xffffffffu, v, o);
    if((t&31)==0) red[t>>5] = v;
    __syncthreads();
    if(t < 32){
        float s = (t < nw) ? red[t] : 0.f;
        #pragma unroll
        for(int o=16;o>0;o>>=1) s += __shfl_down_sync(0xffffffffu, s, o);
        if(t==0) red[0] = s;
    }
    __syncthreads();
    float s = red[0];
    __syncthreads();
    return s;
}

__device__ __forceinline__ float block_reduce_max(float v, float* red){
    int t = threadIdx.x;
    int nw = blockDim.x >> 5;
    #pragma unroll
    for(int o=16;o>0;o>>=1) v = fmaxf(v, __shfl_down_sync(0xffffffffu, v, o));
    if((t&31)==0) red[t>>5] = v;
    __syncthreads();
    if(t < 32){
        float s = (t < nw) ? red[t] : -3.402823466e38f;
        #pragma unroll
        for(int o=16;o>0;o>>=1) s = fmaxf(s, __shfl_down_sync(0xffffffffu, s, o));
        if(t==0) red[0] = s;
    }
    __syncthreads();
    float s = red[0];
    __syncthreads();
    return s;
}

// =====================================================================
// K1: generator front:  h2 = relu(LN(relu(LN(x@gW1+gb1))@gW2+gb2))
// one block per batch row b, 256 threads
// =====================================================================
__global__ __launch_bounds__(256) void k_gen_front(
    const float* __restrict__ x,
    const float* __restrict__ gW1, const float* __restrict__ gb1,
    const float* __restrict__ ln1s, const float* __restrict__ ln1b,
    const float* __restrict__ gW2, const float* __restrict__ gb2,
    const float* __restrict__ ln2s, const float* __restrict__ ln2b)
{
    const int b = blockIdx.x, t = threadIdx.x;
    __shared__ float xs[Dn];
    __shared__ float h1[2*Hn];   // 512
    __shared__ float red[32];

    for(int i=t;i<Dn;i+=256) xs[i] = x[b*Dn+i];
    __syncthreads();

    float a0 = gb1[t], a1 = gb1[t+256];
    #pragma unroll 4
    for(int d=0; d<Dn; ++d){
        float xv = xs[d];
        a0 = fmaf(xv, gW1[d*512 + t      ], a0);
        a1 = fmaf(xv, gW1[d*512 + t + 256], a1);
    }
    float mu = block_reduce_sum(a0+a1, red) * (1.f/512.f);
    float d0 = a0-mu, d1 = a1-mu;
    float var = block_reduce_sum(d0*d0 + d1*d1, red) * (1.f/512.f);
    float rs = rsqrtf(var + EPSf);
    h1[t]     = fmaxf(d0*rs*ln1s[t]     + ln1b[t],     0.f);
    h1[t+256] = fmaxf(d1*rs*ln1s[t+256] + ln1b[t+256], 0.f);
    __syncthreads();

    float a = gb2[t];
    #pragma unroll 4
    for(int k=0;k<512;++k) a = fmaf(h1[k], gW2[k*256 + t], a);
    float mu2 = block_reduce_sum(a, red) * (1.f/256.f);
    float dd = a - mu2;
    float v2 = block_reduce_sum(dd*dd, red) * (1.f/256.f);
    float h2v = fmaxf(dd*rsqrtf(v2+EPSf)*ln2s[t] + ln2b[t], 0.f);
    g_h2t[t*Bn + b] = h2v;   // transposed for GEMM
}

// =====================================================================
// K2a: logits GEMM:  C[128, 102400] = h2[128,256] @ gW3[256,102400] + gb3
// block tile 128(b) x 128(n), 256 threads, 8x8 microtile, k-chunks of 32
// =====================================================================
__global__ __launch_bounds__(256) void k_gemm_logits(
    const float* __restrict__ W, const float* __restrict__ gb3,
    float* __restrict__ logits)
{
    const int n0 = blockIdx.x * 128;
    const int t  = threadIdx.x;
    __shared__ __align__(16) float As[32][128];
    __shared__ __align__(16) float Ws[32][132];

    const int b0 = (t >> 4) * 8;     // 0..120
    const int d0 = (t & 15) * 8;     // 0..120

    float acc[8][8];
    #pragma unroll
    for(int i=0;i<8;i++)
        #pragma unroll
        for(int j=0;j<8;j++) acc[i][j] = 0.f;

    for(int kc=0; kc<Hn; kc+=32){
        // A chunk: As[kk][bb] = h2t[(kc+kk)*128 + bb]   (coalesced, no conflicts)
        #pragma unroll
        for(int i=t; i<32*128; i+=256){
            int kk = i >> 7, bb = i & 127;
            As[kk][bb] = g_h2t[(kc+kk)*Bn + bb];
        }
        // W chunk: Ws[kk][dd] = W[(kc+kk)*102400 + n0 + dd]  (float4)
        #pragma unroll
        for(int i=t; i<32*32; i+=256){
            int kk = i >> 5, v4 = i & 31;
            float4 w4 = __ldg((const float4*)(W + (size_t)(kc+kk)*MD + n0) + v4);
            *((float4*)&Ws[kk][v4*4]) = w4;
        }
        __syncthreads();

        #pragma unroll
        for(int k=0;k<32;k++){
            float ra[8], rw[8];
            *((float4*)&ra[0]) = *((const float4*)&As[k][b0]);
            *((float4*)&ra[4]) = *((const float4*)&As[k][b0+4]);
            *((float4*)&rw[0]) = *((const float4*)&Ws[k][d0]);
            *((float4*)&rw[4]) = *((const float4*)&Ws[k][d0+4]);
            #pragma unroll
            for(int i=0;i<8;i++)
                #pragma unroll
                for(int j=0;j<8;j++)
                    acc[i][j] = fmaf(ra[i], rw[j], acc[i][j]);
        }
        __syncthreads();
    }

    // epilogue: +gb3, write logits
    #pragma unroll
    for(int i=0;i<8;i++){
        size_t base = (size_t)(b0+i)*MD + n0 + d0;
        #pragma unroll
        for(int j=0;j<8;j+=4){
            float4 o;
            o.x = acc[i][j+0] + gb3[n0+d0+j+0];
            o.y = acc[i][j+1] + gb3[n0+d0+j+1];
            o.z = acc[i][j+2] + gb3[n0+d0+j+2];
            o.w = acc[i][j+3] + gb3[n0+d0+j+3];
            *((float4*)(logits + base + j)) = o;
        }
    }
}

// =====================================================================
// K2b: per (b,m) row: z=(logits+gumbel)*2 ; probs=softmax(z) ; top-5 of z
// one block (128 threads) per row, 8 elements/thread
// =====================================================================
__global__ __launch_bounds__(128) void k_softmax_topk(
    const float* __restrict__ logits, const float* __restrict__ gumbel,
    const float* __restrict__ x, float* __restrict__ probs)
{
    const int row = blockIdx.x;          // b*M + m
    const int b   = row / Mn;
    const int t   = threadIdx.x;
    const float4* l4 = (const float4*)(logits + (size_t)row*Dn);
    const float4* g4 = (const float4*)(gumbel + (size_t)row*Dn);

    float s[8];
    {
        float4 a = l4[t*2],   c = g4[t*2];
        float4 a2= l4[t*2+1], c2= g4[t*2+1];
        s[0]=(a.x+c.x)*2.f;  s[1]=(a.y+c.y)*2.f;  s[2]=(a.z+c.z)*2.f;  s[3]=(a.w+c.w)*2.f;
        s[4]=(a2.x+c2.x)*2.f;s[5]=(a2.y+c2.y)*2.f;s[6]=(a2.z+c2.z)*2.f;s[7]=(a2.w+c2.w)*2.f;
    }

    __shared__ float red[32];
    float mx = s[0];
    #pragma unroll
    for(int i=1;i<8;i++) mx = fmaxf(mx, s[i]);
    mx = block_reduce_max(mx, red);

    float e[8]; float sum = 0.f;
    #pragma unroll
    for(int i=0;i<8;i++){ e[i] = expf(s[i]-mx); sum += e[i]; }
    sum = block_reduce_sum(sum, red);
    float inv = 1.f/sum;

    float4* p4 = (float4*)(probs + (size_t)row*Dn);
    float4 p0 = make_float4(e[0]*inv, e[1]*inv, e[2]*inv, e[3]*inv);
    float4 p1 = make_float4(e[4]*inv, e[5]*inv, e[6]*inv, e[7]*inv);
    p4[t*2]   = p0;
    p4[t*2+1] = p1;

    // ---- top-5 via 5 masked argmax passes, jax tie-break (lower index) ----
    __shared__ float rv[4];
    __shared__ int   ri[4];
    __shared__ int   sel;
    const int base_d = t*8;
    for(int r=0;r<KSEL;r++){
        float bv = -3.402823466e38f; int bi = Dn;
        #pragma unroll
        for(int i=0;i<8;i++){
            if(s[i] > bv || (s[i] == bv && base_d+i < bi)){ bv = s[i]; bi = base_d+i; }
        }
        #pragma unroll
        for(int o=16;o>0;o>>=1){
            float ov = __shfl_down_sync(0xffffffffu, bv, o);
            int   oi = __shfl_down_sync(0xffffffffu, bi, o);
            if(ov > bv || (ov == bv && oi < bi)){ bv = ov; bi = oi; }
        }
        if((t&31)==0){ rv[t>>5] = bv; ri[t>>5] = bi; }
        __syncthreads();
        if(t==0){
            #pragma unroll
            for(int w=1;w<4;w++){
                if(rv[w] > bv || (rv[w] == bv && ri[w] < bi)){ bv = rv[w]; bi = ri[w]; }
            }
            sel = bi;
            g_idx[row*KSEL + r] = bi;
            g_val[row*KSEL + r] = x[b*Dn + bi];
        }
        __syncthreads();
        int sd = sel;
        if(sd >= base_d && sd < base_d+8) s[sd-base_d] = -3.402823466e38f;
        __syncthreads();
    }
}

// =====================================================================
// K3: scorer + synergy heads, 16 (b,m)-rows per block, 256 threads
// =====================================================================
#define R3 16
__global__ __launch_bounds__(256) void k_heads(
    const float* __restrict__ sW1, const float* __restrict__ sb1,
    const float* __restrict__ sW2, const float* __restrict__ sb2,
    const float* __restrict__ sW3, const float* __restrict__ sb3,
    const float* __restrict__ yW1, const float* __restrict__ yb1,
    const float* __restrict__ yW2, const float* __restrict__ yb2,
    float* __restrict__ scores, float* __restrict__ syns)
{
    const int row0 = blockIdx.x * R3;
    const int t = threadIdx.x;
    __shared__ float hs[R3][Hn];     // 16 KB
    __shared__ float hy[R3][Hn];     // 16 KB
    __shared__ float h2s[R3][128];   // 8 KB
    __shared__ int   sidx[R3][KSEL];
    __shared__ float sval[R3][KSEL];

    if(t < R3*KSEL){
        int r = t / KSEL, j = t % KSEL;
        sidx[r][j] = g_idx[(row0+r)*KSEL + j];
        sval[r][j] = g_val[(row0+r)*KSEL + j];
    }
    __syncthreads();

    // stage 1: hs/hy = relu(sum_j val_j * W1[row_j, :] + b1)  (5-sparse gather)
    for(int r=0;r<R3;r++){
        float a = sb1[t], c = yb1[t];
        #pragma unroll
        for(int j=0;j<KSEL;j++){
            size_t w = (size_t)(j*Dn + sidx[r][j]) * Hn + t;
            float v = sval[r][j];
            a = fmaf(v, __ldg(sW1 + w), a);
            c = fmaf(v, __ldg(yW1 + w), c);
        }
        hs[r][t] = fmaxf(a, 0.f);
        hy[r][t] = fmaxf(c, 0.f);
    }
    __syncthreads();

    // stage 2: h2s[r] = relu(hs[r] @ sW2 + sb2), 8 rows per half-block
    {
        const int c  = t & 127;
        const int rb = (t >> 7) * 8;
        float acc[8] = {0,0,0,0,0,0,0,0};
        for(int k=0;k<Hn;k++){
            float w = __ldg(sW2 + k*128 + c);
            #pragma unroll
            for(int rr=0;rr<8;rr++) acc[rr] = fmaf(hs[rb+rr][k], w, acc[rr]);
        }
        float bb = sb2[c];
        #pragma unroll
        for(int rr=0;rr<8;rr++) h2s[rb+rr][c] = fmaxf(acc[rr] + bb, 0.f);
    }
    __syncthreads();

    // stage 3: final dots, 16 threads per row
    {
        const int r = t >> 4;     // 0..15
        const int g = t & 15;     // 0..15
        float ds = 0.f, dy = 0.f;
        #pragma unroll
        for(int i=0;i<8;i++)  ds = fmaf(h2s[r][g*8+i],  sW3[g*8+i],  ds);
        #pragma unroll
        for(int i=0;i<16;i++) dy = fmaf(hy[r][g*16+i], yW2[g*16+i], dy);
        #pragma unroll
        for(int o=8;o>0;o>>=1){
            ds += __shfl_down_sync(0xffffffffu, ds, o, 16);
            dy += __shfl_down_sync(0xffffffffu, dy, o, 16);
        }
        if(g==0){
            scores[row0+r] = 1.f/(1.f + expf(-(ds + sb3[0])));
            syns[row0+r]   = tanhf(dy + yb2[0]);
        }
    }
}

// =====================================================================
extern "C" void kernel_launch(void* const* d_in, const int* in_sizes, int n_in,
                              void* d_out, int out_size)
{
    const float* x    = (const float*)d_in[0];
    const float* gum  = (const float*)d_in[1];
    const float* gW1  = (const float*)d_in[2];
    const float* gb1  = (const float*)d_in[3];
    const float* ln1s = (const float*)d_in[4];
    const float* ln1b = (const float*)d_in[5];
    const float* gW2  = (const float*)d_in[6];
    const float* gb2  = (const float*)d_in[7];
    const float* ln2s = (const float*)d_in[8];
    const float* ln2b = (const float*)d_in[9];
    const float* gW3  = (const float*)d_in[10];
    const float* gb3  = (const float*)d_in[11];
    const float* sW1  = (const float*)d_in[12];
    const float* sb1  = (const float*)d_in[13];
    const float* sW2  = (const float*)d_in[14];
    const float* sb2  = (const float*)d_in[15];
    const float* sW3  = (const float*)d_in[16];
    const float* sb3  = (const float*)d_in[17];
    const float* yW1  = (const float*)d_in[18];
    const float* yb1  = (const float*)d_in[19];
    const float* yW2  = (const float*)d_in[20];
    const float* yb2  = (const float*)d_in[21];

    float* out    = (float*)d_out;
    float* probs  = out;                               // [B,M,D]
    float* scores = out + (size_t)Bn*Mn*Dn;            // [B,M]
    float* syns   = scores + Bn*Mn;                    // [B,M]
    float* logits = syns + Bn*Mn;                      // [B,M,D]

    k_gen_front<<<Bn, 256>>>(x, gW1, gb1, ln1s, ln1b, gW2, gb2, ln2s, ln2b);
    k_gemm_logits<<<MD/128, 256>>>(gW3, gb3, logits);
    k_softmax_topk<<<Bn*Mn, 128>>>(logits, gum, x, probs);
    k_heads<<<(Bn*Mn)/R3, 256>>>(sW1, sb1, sW2, sb2, sW3, sb3,
                                 yW1, yb1, yW2, yb2, scores, syns);
}